// round 4
// baseline (speedup 1.0000x reference)
#include <cuda_runtime.h>
#include <math_constants.h>
#include <cstdint>

// ---------------------------------------------------------------------------
// DIMES dense encoder, B=16, N=200, U=64, L=3  — recompute scheme, no z tensor
// ---------------------------------------------------------------------------

constexpr int B_ = 16, N_ = 200, M_ = 199, U_ = 64;
constexpr int BN_ = B_ * N_;                     // 3200
constexpr long long E_ = (long long)BN_ * M_;    // 636800 edge rows
constexpr float EPS_ = 1e-5f;

__device__ __align__(16) float g_w[(size_t)636800 * 64];
__device__ __align__(16) float g_h[BN_ * U_];
__device__ __align__(16) float g_xbuf[2][4][BN_ * U_];   // x1,x2,x3,x4 ping-pong
__device__ __align__(16) float g_pooled[BN_ * U_];
__device__ double g_estats[2 * U_];
__device__ double g_hstats[2 * U_];
__device__ __align__(16) float g_ecoef[2 * U_];  // scale, shift
__device__ __align__(16) float g_hcoef[2 * U_];

// dynamic smem layout (floats)
constexpr int SM_W0 = 0;            // 64*68
constexpr int SM_W1 = 4352;         // 64*68
constexpr int SM_Z  = 8704;         // 64*68
constexpr int SM_EP = 13056;        // 64*72
constexpr int SM_EC = 17664;        // 64*72
constexpr int SM_RED= 22272;        // 16*68
constexpr int SM_ADJ= 23360;        // 208
constexpr int SM_FLOATS = 23568;
constexpr size_t SMEM_BYTES = SM_FLOATS * 4;

__device__ __forceinline__ float lrelu(float v) { return v >= 0.f ? v : 0.01f * v; }

__device__ __forceinline__ unsigned to_tf32(float f) {
    unsigned r;
    asm("cvt.rna.tf32.f32 %0, %1;" : "=r"(r) : "f"(f));
    return r;
}

__device__ __forceinline__ void mma_tf32(float c[4], unsigned a0, unsigned a1,
                                         unsigned a2, unsigned a3,
                                         unsigned b0, unsigned b1) {
    asm volatile(
        "mma.sync.aligned.m16n8k8.row.col.f32.tf32.tf32.f32 "
        "{%0,%1,%2,%3}, {%4,%5,%6,%7}, {%8,%9}, {%0,%1,%2,%3};"
        : "+f"(c[0]), "+f"(c[1]), "+f"(c[2]), "+f"(c[3])
        : "r"(a0), "r"(a1), "r"(a2), "r"(a3), "r"(b0), "r"(b1));
}

__device__ __forceinline__ void cp_async16(unsigned dst, const void* src) {
    asm volatile("cp.async.cg.shared.global [%0], [%1], 16;" :: "r"(dst), "l"(src));
}
__device__ __forceinline__ void cp_commit() { asm volatile("cp.async.commit_group;"); }
template<int K> __device__ __forceinline__ void cp_wait() {
    asm volatile("cp.async.wait_group %0;" :: "n"(K));
}

// GEMM: C(64x64) = W(64x64, fp32 in smem, cvt to tf32 on load) @ E(tf32 in smem)
__device__ __forceinline__ void do_gemm(const float* __restrict__ W,
                                        const float* __restrict__ Em,
                                        float cf[4][4], int mrow, int ncol0, int tig) {
#pragma unroll
    for (int nt = 0; nt < 4; nt++) { cf[nt][0]=0.f; cf[nt][1]=0.f; cf[nt][2]=0.f; cf[nt][3]=0.f; }
#pragma unroll
    for (int k0 = 0; k0 < 64; k0 += 8) {
        unsigned a0 = to_tf32(W[mrow * 68 + k0 + tig]);
        unsigned a1 = to_tf32(W[(mrow + 8) * 68 + k0 + tig]);
        unsigned a2 = to_tf32(W[mrow * 68 + k0 + tig + 4]);
        unsigned a3 = to_tf32(W[(mrow + 8) * 68 + k0 + tig + 4]);
#pragma unroll
        for (int nt = 0; nt < 4; nt++) {
            int col = ncol0 + nt * 8 + ((threadIdx.x & 31) >> 2);
            unsigned b0 = __float_as_uint(Em[(k0 + tig) * 72 + col]);
            unsigned b1 = __float_as_uint(Em[(k0 + tig + 4) * 72 + col]);
            mma_tf32(cf[nt], a0, a1, a2, a3, b0, b1);
        }
    }
}

__device__ __forceinline__ void stage_z(float* __restrict__ z_sh, float cf[4][4],
                                        int mrow, int ncol0, int tig) {
#pragma unroll
    for (int nt = 0; nt < 4; nt++) {
        int cc = ncol0 + nt * 8 + 2 * tig;
        *(float2*)&z_sh[mrow * 68 + cc]       = make_float2(cf[nt][0], cf[nt][1]);
        *(float2*)&z_sh[(mrow + 8) * 68 + cc] = make_float2(cf[nt][2], cf[nt][3]);
    }
}

// ---------------------------------------------------------------------------
// Unified edge kernel. One block per (b,n), 256 threads.
// INIT:  compute w0 from adj (write w), no prev
// PREV:  recompute z_prev (GEMM with EwP) and apply bn_prev residual to w
// STATS: compute z_cur (GEMM with Ew), accumulate BN stats
// POOLED: compute pooled max + h BN stats
// LAST:  apply bn_prev and project to output (no w write, no stats)
// ---------------------------------------------------------------------------
template<bool INIT, bool PREV, bool STATS, bool POOLED, bool LAST>
__global__ void __launch_bounds__(256) k_edge(
    const float* __restrict__ adj, const float* __restrict__ ew0, const float* __restrict__ eb0,
    const float* __restrict__ EwP, const float* __restrict__ EbP, int bufP,
    const float* __restrict__ Ew,  const float* __restrict__ Eb,  int bufC,
    const float* __restrict__ e1w, const float* __restrict__ e1b,
    float* __restrict__ out)
{
    extern __shared__ float sm[];
    float* w_sh0 = sm + SM_W0;
    float* w_sh1 = sm + SM_W1;
    float* z_sh  = sm + SM_Z;
    float* e_shP = sm + SM_EP;
    float* e_shC = sm + SM_EC;
    float* red   = sm + SM_RED;
    float* adj_sh= sm + SM_ADJ;

    const int bn = blockIdx.x, n = bn % N_, b = bn / N_;
    const int t = threadIdx.x, c = t & 15, r = t >> 4, c4 = c * 4;
    const int lane = t & 31, wp = t >> 5, grp = lane >> 2, tig = lane & 3;
    const int mrow = (wp & 3) * 16 + grp, ncol0 = (wp >> 2) * 32;

    float* wbase = g_w + (size_t)bn * M_ * U_;

    // weight matrices -> smem (tf32)
    if (PREV || LAST) {
        for (int idx = t; idx < 1024; idx += 256) {
            int k = idx >> 4, q = (idx & 15) * 4;
            float4 v = __ldg((const float4*)&EwP[k * 64 + q]);
            v.x = __uint_as_float(to_tf32(v.x)); v.y = __uint_as_float(to_tf32(v.y));
            v.z = __uint_as_float(to_tf32(v.z)); v.w = __uint_as_float(to_tf32(v.w));
            *(float4*)&e_shP[k * 72 + q] = v;
        }
    }
    if (STATS) {
        for (int idx = t; idx < 1024; idx += 256) {
            int k = idx >> 4, q = (idx & 15) * 4;
            float4 v = __ldg((const float4*)&Ew[k * 64 + q]);
            v.x = __uint_as_float(to_tf32(v.x)); v.y = __uint_as_float(to_tf32(v.y));
            v.z = __uint_as_float(to_tf32(v.z)); v.w = __uint_as_float(to_tf32(v.w));
            *(float4*)&e_shC[k * 72 + q] = v;
        }
    }
    if (INIT) {
        for (int i = t; i < M_; i += 256) {
            int dst = i + (i >= n);
            adj_sh[i] = __ldg(&adj[(size_t)bn * N_ + dst]);
        }
    }

    // per-thread constants
    float4 zcP, s4, sh4, zcC, ew04, eb04, e1w4;
    float e1b0 = 0.f;
    if (PREV || LAST) {
        float4 e = __ldg((const float4*)&EbP[c4]);
        float4 x3v = *(const float4*)&g_xbuf[bufP][2][bn * U_ + c4];
        zcP = make_float4(e.x + x3v.x, e.y + x3v.y, e.z + x3v.z, e.w + x3v.w);
        s4  = *(const float4*)&g_ecoef[c4];
        sh4 = *(const float4*)&g_ecoef[U_ + c4];
    }
    if (STATS) {
        float4 e = __ldg((const float4*)&Eb[c4]);
        float4 x3v = *(const float4*)&g_xbuf[bufC][2][bn * U_ + c4];
        zcC = make_float4(e.x + x3v.x, e.y + x3v.y, e.z + x3v.z, e.w + x3v.w);
    }
    if (INIT) {
        ew04 = __ldg((const float4*)&ew0[c4]);
        eb04 = __ldg((const float4*)&eb0[c4]);
    }
    if (LAST) {
        e1w4 = __ldg((const float4*)&e1w[c4]);
        e1b0 = __ldg(&e1b[0]);
    }

    const float* x2C = STATS ? &g_xbuf[bufC][1][(size_t)b * N_ * U_] : nullptr;
    const float* x4C = STATS ? &g_xbuf[bufC][3][(size_t)b * N_ * U_] : nullptr;
    const float* x4P = (PREV || LAST) ? &g_xbuf[bufP][3][(size_t)b * N_ * U_] : nullptr;

    float4 pool = make_float4(-CUDART_INF_F, -CUDART_INF_F, -CUDART_INF_F, -CUDART_INF_F);
    float4 esum = make_float4(0.f, 0.f, 0.f, 0.f);
    float4 esq  = make_float4(0.f, 0.f, 0.f, 0.f);

    // prologue: prefetch tile 0
    if (!INIT) {
#pragma unroll
        for (int k = 0; k < 4; k++) {
            int idx = t + k * 256, rr = idx >> 4, q = (idx & 15) * 4;
            cp_async16((unsigned)__cvta_generic_to_shared(&w_sh0[rr * 68 + q]),
                       &wbase[(size_t)rr * 64 + q]);
        }
        cp_commit();
    }

#pragma unroll 1
    for (int tile = 0; tile < 4; tile++) {
        const int m0 = tile * 64;
        float* W = INIT ? w_sh0 : ((tile & 1) ? w_sh1 : w_sh0);

        if (!INIT) {
            if (tile < 3) {
                float* Wn = (tile & 1) ? w_sh0 : w_sh1;
                int m0n = m0 + 64;
                int rowsn = min(64, M_ - m0n);
#pragma unroll
                for (int k = 0; k < 4; k++) {
                    int idx = t + k * 256, rr = idx >> 4, q = (idx & 15) * 4;
                    if (rr < rowsn)
                        cp_async16((unsigned)__cvta_generic_to_shared(&Wn[rr * 68 + q]),
                                   &wbase[(size_t)(m0n + rr) * 64 + q]);
                }
                cp_commit();
                cp_wait<1>();
            } else {
                cp_wait<0>();
            }
        }
        __syncthreads();

        if (INIT) {
            // compute initial w tile and write to global
#pragma unroll
            for (int j = 0; j < 4; j++) {
                int rr = 4 * r + j, m = m0 + rr;
                if (m < M_) {
                    float a = adj_sh[m];
                    float4 w4;
                    w4.x = lrelu(fmaf(a, ew04.x, eb04.x));
                    w4.y = lrelu(fmaf(a, ew04.y, eb04.y));
                    w4.z = lrelu(fmaf(a, ew04.z, eb04.z));
                    w4.w = lrelu(fmaf(a, ew04.w, eb04.w));
                    *(float4*)&W[rr * 68 + c4] = w4;
                    *(float4*)&wbase[(size_t)m * 64 + c4] = w4;
                }
            }
            __syncthreads();
        }

        if (PREV || LAST) {
            // GEMM_A: z_prev = w @ EwP
            float cfP[4][4];
            do_gemm(W, e_shP, cfP, mrow, ncol0, tig);
            stage_z(z_sh, cfP, mrow, ncol0, tig);
            __syncthreads();
            if (LAST) {
                float pj[4];
#pragma unroll
                for (int j = 0; j < 4; j++) {
                    int rr = 4 * r + j, m = m0 + rr;
                    pj[j] = 0.f;
                    if (m < M_) {
                        int dst = m + (m >= n);
                        float4 z4 = *(const float4*)&z_sh[rr * 68 + c4];
                        float4 x4v = __ldg((const float4*)&x4P[dst * U_ + c4]);
                        float4 w4 = *(const float4*)&W[rr * 68 + c4];
                        float wn;
                        wn = w4.x + lrelu(fmaf(z4.x + (zcP.x + x4v.x), s4.x, sh4.x));
                        pj[j] = wn * e1w4.x;
                        wn = w4.y + lrelu(fmaf(z4.y + (zcP.y + x4v.y), s4.y, sh4.y));
                        pj[j] += wn * e1w4.y;
                        wn = w4.z + lrelu(fmaf(z4.z + (zcP.z + x4v.z), s4.z, sh4.z));
                        pj[j] += wn * e1w4.z;
                        wn = w4.w + lrelu(fmaf(z4.w + (zcP.w + x4v.w), s4.w, sh4.w));
                        pj[j] += wn * e1w4.w;
                    }
                }
#pragma unroll
                for (int j = 0; j < 4; j++) {
#pragma unroll
                    for (int off = 1; off < 16; off <<= 1)
                        pj[j] += __shfl_xor_sync(0xffffffffu, pj[j], off);
                }
                if (c == 0) {
#pragma unroll
                    for (int j = 0; j < 4; j++) {
                        int m = m0 + 4 * r + j;
                        if (m < M_) {
                            int dst = m + (m >= n);
                            out[((size_t)bn) * N_ + dst] = pj[j] + e1b0;
                        }
                    }
                }
            } else {
                // apply residual BN update to w tile, write back to global
#pragma unroll
                for (int j = 0; j < 4; j++) {
                    int rr = 4 * r + j, m = m0 + rr;
                    if (m < M_) {
                        int dst = m + (m >= n);
                        float4 z4 = *(const float4*)&z_sh[rr * 68 + c4];
                        float4 x4v = __ldg((const float4*)&x4P[dst * U_ + c4]);
                        float4 w4 = *(const float4*)&W[rr * 68 + c4];
                        w4.x += lrelu(fmaf(z4.x + (zcP.x + x4v.x), s4.x, sh4.x));
                        w4.y += lrelu(fmaf(z4.y + (zcP.y + x4v.y), s4.y, sh4.y));
                        w4.z += lrelu(fmaf(z4.z + (zcP.z + x4v.z), s4.z, sh4.z));
                        w4.w += lrelu(fmaf(z4.w + (zcP.w + x4v.w), s4.w, sh4.w));
                        *(float4*)&W[rr * 68 + c4] = w4;
                        *(float4*)&wbase[(size_t)m * 64 + c4] = w4;
                    }
                }
                __syncthreads();
            }
        }

        if (POOLED) {
#pragma unroll
            for (int j = 0; j < 4; j++) {
                int rr = 4 * r + j, m = m0 + rr;
                if (m < M_) {
                    int dst = m + (m >= n);
                    float4 x2v = __ldg((const float4*)&x2C[dst * U_ + c4]);
                    float4 wv = *(const float4*)&W[rr * 68 + c4];
                    pool.x = fmaxf(pool.x, x2v.x / (1.f + __expf(-wv.x)));
                    pool.y = fmaxf(pool.y, x2v.y / (1.f + __expf(-wv.y)));
                    pool.z = fmaxf(pool.z, x2v.z / (1.f + __expf(-wv.z)));
                    pool.w = fmaxf(pool.w, x2v.w / (1.f + __expf(-wv.w)));
                }
            }
        }

        if (STATS) {
            float cf[4][4];
            do_gemm(W, e_shC, cf, mrow, ncol0, tig);
            __syncthreads();   // prior z_sh readers done (apply epi synced; safe for S0 too)
            stage_z(z_sh, cf, mrow, ncol0, tig);
            __syncthreads();
#pragma unroll
            for (int j = 0; j < 4; j++) {
                int rr = 4 * r + j, m = m0 + rr;
                if (m < M_) {
                    int dst = m + (m >= n);
                    float4 z4 = *(const float4*)&z_sh[rr * 68 + c4];
                    float4 x4v = __ldg((const float4*)&x4C[dst * U_ + c4]);
                    float z;
                    z = z4.x + (zcC.x + x4v.x); esum.x += z; esq.x = fmaf(z, z, esq.x);
                    z = z4.y + (zcC.y + x4v.y); esum.y += z; esq.y = fmaf(z, z, esq.y);
                    z = z4.z + (zcC.z + x4v.z); esum.z += z; esq.z = fmaf(z, z, esq.z);
                    z = z4.w + (zcC.w + x4v.w); esum.w += z; esq.w = fmaf(z, z, esq.w);
                }
            }
        }
        __syncthreads();
    }

    // ---- block reductions ----
    if (POOLED) {
        *(float4*)&red[r * 68 + c4] = pool;
        __syncthreads();
#pragma unroll
        for (int s = 8; s >= 1; s >>= 1) {
            if (r < s) {
                float4 a = *(float4*)&red[r * 68 + c4];
                float4 bb = *(float4*)&red[(r + s) * 68 + c4];
                a.x = fmaxf(a.x, bb.x); a.y = fmaxf(a.y, bb.y);
                a.z = fmaxf(a.z, bb.z); a.w = fmaxf(a.w, bb.w);
                *(float4*)&red[r * 68 + c4] = a;
            }
            __syncthreads();
        }
        if (r == 0) {
            float4 p = *(float4*)&red[c4];
            *(float4*)&g_pooled[bn * U_ + c4] = p;
            float4 x1v = *(const float4*)&g_xbuf[bufC][0][bn * U_ + c4];
            float zh;
            zh = x1v.x + p.x; atomicAdd(&g_hstats[c4 + 0], (double)zh); atomicAdd(&g_hstats[U_ + c4 + 0], (double)(zh * zh));
            zh = x1v.y + p.y; atomicAdd(&g_hstats[c4 + 1], (double)zh); atomicAdd(&g_hstats[U_ + c4 + 1], (double)(zh * zh));
            zh = x1v.z + p.z; atomicAdd(&g_hstats[c4 + 2], (double)zh); atomicAdd(&g_hstats[U_ + c4 + 2], (double)(zh * zh));
            zh = x1v.w + p.w; atomicAdd(&g_hstats[c4 + 3], (double)zh); atomicAdd(&g_hstats[U_ + c4 + 3], (double)(zh * zh));
        }
        __syncthreads();
    }
    if (STATS) {
        *(float4*)&red[r * 68 + c4] = esum;
        __syncthreads();
#pragma unroll
        for (int s = 8; s >= 1; s >>= 1) {
            if (r < s) {
                float4 a = *(float4*)&red[r * 68 + c4];
                float4 bb = *(float4*)&red[(r + s) * 68 + c4];
                a.x += bb.x; a.y += bb.y; a.z += bb.z; a.w += bb.w;
                *(float4*)&red[r * 68 + c4] = a;
            }
            __syncthreads();
        }
        if (r == 0) {
            float4 sv = *(float4*)&red[c4];
            atomicAdd(&g_estats[c4 + 0], (double)sv.x);
            atomicAdd(&g_estats[c4 + 1], (double)sv.y);
            atomicAdd(&g_estats[c4 + 2], (double)sv.z);
            atomicAdd(&g_estats[c4 + 3], (double)sv.w);
        }
        __syncthreads();
        *(float4*)&red[r * 68 + c4] = esq;
        __syncthreads();
#pragma unroll
        for (int s = 8; s >= 1; s >>= 1) {
            if (r < s) {
                float4 a = *(float4*)&red[r * 68 + c4];
                float4 bb = *(float4*)&red[(r + s) * 68 + c4];
                a.x += bb.x; a.y += bb.y; a.z += bb.z; a.w += bb.w;
                *(float4*)&red[r * 68 + c4] = a;
            }
            __syncthreads();
        }
        if (r == 0) {
            float4 sv = *(float4*)&red[c4];
            atomicAdd(&g_estats[U_ + c4 + 0], (double)sv.x);
            atomicAdd(&g_estats[U_ + c4 + 1], (double)sv.y);
            atomicAdd(&g_estats[U_ + c4 + 2], (double)sv.z);
            atomicAdd(&g_estats[U_ + c4 + 3], (double)sv.w);
        }
    }
}

// ---------------------------------------------------------------------------
// Node-path kernel: (optional h update) + x1..x4 GEMVs. One block per (b,n).
// ---------------------------------------------------------------------------
__global__ void __launch_bounds__(256) k_node(
    const float* __restrict__ x, const float* __restrict__ l0w, const float* __restrict__ l0b,
    int first, int prevBuf, int outBuf,
    const float* __restrict__ w1, const float* __restrict__ b1,
    const float* __restrict__ w2, const float* __restrict__ b2,
    const float* __restrict__ w3, const float* __restrict__ b3,
    const float* __restrict__ w4, const float* __restrict__ b4)
{
    __shared__ float hsh[U_];
    int bn = blockIdx.x, t = threadIdx.x;
    if (t < U_) {
        float hv;
        if (first) {
            hv = lrelu(x[bn * 2] * l0w[t] + x[bn * 2 + 1] * l0w[U_ + t] + l0b[t]);
        } else {
            float zh = g_xbuf[prevBuf][0][bn * U_ + t] + g_pooled[bn * U_ + t];
            hv = g_h[bn * U_ + t] + lrelu(fmaf(zh, g_hcoef[t], g_hcoef[U_ + t]));
        }
        hsh[t] = hv;
        g_h[bn * U_ + t] = hv;
    }
    __syncthreads();
    int mat = t >> 6, col = t & 63;
    const float* W; const float* bb;
    switch (mat) {
        case 0:  W = w1; bb = b1; break;
        case 1:  W = w2; bb = b2; break;
        case 2:  W = w3; bb = b3; break;
        default: W = w4; bb = b4; break;
    }
    float acc = __ldg(&bb[col]);
#pragma unroll
    for (int k = 0; k < U_; k++) acc = fmaf(hsh[k], __ldg(&W[k * U_ + col]), acc);
    g_xbuf[outBuf][mat][bn * U_ + col] = acc;
}

__global__ void k_finalize(const float* __restrict__ hg, const float* __restrict__ hb,
                           const float* __restrict__ eg, const float* __restrict__ eb) {
    int u = threadIdx.x;  // 64
    double ecnt = (double)E_;
    float emean = (float)(g_estats[u] / ecnt);
    float evar  = (float)(g_estats[U_ + u] / ecnt) - emean * emean;
    float es = eg[u] * rsqrtf(evar + EPS_);
    g_ecoef[u] = es;
    g_ecoef[U_ + u] = eb[u] - emean * es;

    double hcnt = (double)BN_;
    float hmean = (float)(g_hstats[u] / hcnt);
    float hvar  = (float)(g_hstats[U_ + u] / hcnt) - hmean * hmean;
    float hs = hg[u] * rsqrtf(hvar + EPS_);
    g_hcoef[u] = hs;
    g_hcoef[U_ + u] = hb[u] - hmean * hs;

    g_estats[u] = 0.0; g_estats[U_ + u] = 0.0;
    g_hstats[u] = 0.0; g_hstats[U_ + u] = 0.0;
}

__global__ void k_zdiag(float* __restrict__ out) {
    int idx = blockIdx.x * 256 + threadIdx.x;
    if (idx >= BN_) return;
    int b = idx / N_, n = idx % N_;
    out[((size_t)(b * N_ + n)) * N_ + n] = 0.f;
}

extern "C" void kernel_launch(void* const* d_in, const int* in_sizes, int n_in,
                              void* d_out, int out_size) {
    const float* x    = (const float*)d_in[0];
    const float* adj  = (const float*)d_in[1];
    const float* vl0w = (const float*)d_in[2];
    const float* vl0b = (const float*)d_in[3];
    const float* vw1  = (const float*)d_in[4];
    const float* vb1  = (const float*)d_in[5];
    const float* vw2  = (const float*)d_in[6];
    const float* vb2  = (const float*)d_in[7];
    const float* vw3  = (const float*)d_in[8];
    const float* vb3  = (const float*)d_in[9];
    const float* vw4  = (const float*)d_in[10];
    const float* vb4  = (const float*)d_in[11];
    const float* vbng = (const float*)d_in[12];
    const float* vbnb = (const float*)d_in[13];
    const float* el0w = (const float*)d_in[14];
    const float* el0b = (const float*)d_in[15];
    const float* ew   = (const float*)d_in[16];
    const float* eb   = (const float*)d_in[17];
    const float* ebng = (const float*)d_in[18];
    const float* ebnb = (const float*)d_in[19];
    const float* e1w  = (const float*)d_in[20];
    const float* e1b  = (const float*)d_in[21];
    float* out = (float*)d_out;

    auto S0 = k_edge<true,  false, true,  true,  false>;
    auto F1 = k_edge<false, true,  true,  true,  false>;
    auto F2 = k_edge<false, true,  true,  false, false>;
    auto AL = k_edge<false, false, false, false, true>;
    cudaFuncSetAttribute((const void*)S0, cudaFuncAttributeMaxDynamicSharedMemorySize, (int)SMEM_BYTES);
    cudaFuncSetAttribute((const void*)F1, cudaFuncAttributeMaxDynamicSharedMemorySize, (int)SMEM_BYTES);
    cudaFuncSetAttribute((const void*)F2, cudaFuncAttributeMaxDynamicSharedMemorySize, (int)SMEM_BYTES);
    cudaFuncSetAttribute((const void*)AL, cudaFuncAttributeMaxDynamicSharedMemorySize, (int)SMEM_BYTES);

    const float* W0 = ew, *B0 = eb;
    const float* W1 = ew + 4096, *B1 = eb + 64;
    const float* W2 = ew + 8192, *B2 = eb + 128;

    // layer 0
    k_node<<<BN_, 256>>>(x, vl0w, vl0b, 1, 0, 0,
                         vw1, vb1, vw2, vb2, vw3, vb3, vw4, vb4);
    S0<<<BN_, 256, SMEM_BYTES>>>(adj, el0w, el0b,
                                 nullptr, nullptr, 0, W0, B0, 0,
                                 nullptr, nullptr, nullptr);
    k_finalize<<<1, 64>>>(vbng, vbnb, ebng, ebnb);

    // layer 1
    k_node<<<BN_, 256>>>(x, vl0w, vl0b, 0, 0, 1,
                         vw1 + 4096, vb1 + 64, vw2 + 4096, vb2 + 64,
                         vw3 + 4096, vb3 + 64, vw4 + 4096, vb4 + 64);
    F1<<<BN_, 256, SMEM_BYTES>>>(nullptr, nullptr, nullptr,
                                 W0, B0, 0, W1, B1, 1,
                                 nullptr, nullptr, nullptr);
    k_finalize<<<1, 64>>>(vbng + 64, vbnb + 64, ebng + 64, ebnb + 64);

    // layer 2
    k_node<<<BN_, 256>>>(x, vl0w, vl0b, 0, 1, 0,
                         vw1 + 8192, vb1 + 128, vw2 + 8192, vb2 + 128,
                         vw3 + 8192, vb3 + 128, vw4 + 8192, vb4 + 128);
    F2<<<BN_, 256, SMEM_BYTES>>>(nullptr, nullptr, nullptr,
                                 W1, B1, 1, W2, B2, 0,
                                 nullptr, nullptr, nullptr);
    k_finalize<<<1, 64>>>(vbng + 128, vbnb + 128, ebng + 128, ebnb + 128);

    // final: apply bn2 + project
    AL<<<BN_, 256, SMEM_BYTES>>>(nullptr, nullptr, nullptr,
                                 W2, B2, 0, nullptr, nullptr, 0,
                                 e1w, e1b, out);
    k_zdiag<<<(BN_ + 255) / 256, 256>>>(out);
}

// round 5
// speedup vs baseline: 1.0840x; 1.0840x over previous
#include <cuda_runtime.h>
#include <math_constants.h>
#include <cstdint>

// ---------------------------------------------------------------------------
// DIMES dense encoder, B=16, N=200, U=64, L=3
// Recompute scheme (no z tensor), tile-split grid, fragment-direct epilogues.
// ---------------------------------------------------------------------------

constexpr int B_ = 16, N_ = 200, M_ = 199, U_ = 64;
constexpr int BN_ = B_ * N_;                     // 3200
constexpr long long E_ = (long long)BN_ * M_;    // 636800 edge rows
constexpr float EPS_ = 1e-5f;

__device__ __align__(16) float g_w[(size_t)636800 * 64];
__device__ __align__(16) float g_h[BN_ * U_];
__device__ __align__(16) float g_xbuf[2][4][BN_ * U_];   // x1,x2,x3,x4 ping-pong
__device__ unsigned g_pooled_u[BN_ * U_];                // order-encoded max
__device__ double g_estats[2 * U_];
__device__ double g_hstats[2 * U_];
__device__ __align__(16) float g_ecoef[2 * U_];  // scale, shift
__device__ __align__(16) float g_hcoef[2 * U_];

__device__ __forceinline__ float lrelu(float v) { return v >= 0.f ? v : 0.01f * v; }

// order-preserving float<->uint for atomicMax
__device__ __forceinline__ unsigned enc_f(float f) {
    unsigned u = __float_as_uint(f);
    return u ^ ((u & 0x80000000u) ? 0xffffffffu : 0x80000000u);
}
__device__ __forceinline__ float dec_f(unsigned k) {
    return __uint_as_float((k & 0x80000000u) ? (k ^ 0x80000000u) : ~k);
}

__device__ __forceinline__ unsigned to_tf32(float f) {
    unsigned r;
    asm("cvt.rna.tf32.f32 %0, %1;" : "=r"(r) : "f"(f));
    return r;
}

__device__ __forceinline__ void mma_tf32(float c[4], unsigned a0, unsigned a1,
                                         unsigned a2, unsigned a3,
                                         unsigned b0, unsigned b1) {
    asm volatile(
        "mma.sync.aligned.m16n8k8.row.col.f32.tf32.tf32.f32 "
        "{%0,%1,%2,%3}, {%4,%5,%6,%7}, {%8,%9}, {%0,%1,%2,%3};"
        : "+f"(c[0]), "+f"(c[1]), "+f"(c[2]), "+f"(c[3])
        : "r"(a0), "r"(a1), "r"(a2), "r"(a3), "r"(b0), "r"(b1));
}

__device__ __forceinline__ void cp_async16(unsigned dst, const void* src) {
    asm volatile("cp.async.cg.shared.global [%0], [%1], 16;" :: "r"(dst), "l"(src));
}
__device__ __forceinline__ void cp_commit() { asm volatile("cp.async.commit_group;"); }
template<int K> __device__ __forceinline__ void cp_wait() {
    asm volatile("cp.async.wait_group %0;" :: "n"(K));
}

// C(64x64) = W(fp32 smem, stride 68, cvt on load) @ E(tf32 smem, stride 72)
__device__ __forceinline__ void do_gemm(const float* __restrict__ W,
                                        const float* __restrict__ Em,
                                        float cf[4][4], int la, int ncol0, int tig) {
    const int grp = (threadIdx.x & 31) >> 2;
#pragma unroll
    for (int nt = 0; nt < 4; nt++) { cf[nt][0]=0.f; cf[nt][1]=0.f; cf[nt][2]=0.f; cf[nt][3]=0.f; }
#pragma unroll
    for (int k0 = 0; k0 < 64; k0 += 8) {
        unsigned a0 = to_tf32(W[la * 68 + k0 + tig]);
        unsigned a1 = to_tf32(W[(la + 8) * 68 + k0 + tig]);
        unsigned a2 = to_tf32(W[la * 68 + k0 + tig + 4]);
        unsigned a3 = to_tf32(W[(la + 8) * 68 + k0 + tig + 4]);
#pragma unroll
        for (int nt = 0; nt < 4; nt++) {
            int col = ncol0 + nt * 8 + grp;
            unsigned b0 = __float_as_uint(Em[(k0 + tig) * 72 + col]);
            unsigned b1 = __float_as_uint(Em[(k0 + tig + 4) * 72 + col]);
            mma_tf32(cf[nt], a0, a1, a2, a3, b0, b1);
        }
    }
}

// ---------------------------------------------------------------------------
// Edge kernel: grid = BN_*4 (one block per (bn, 64-row tile)). 256 threads.
// INIT:  build w0 tile from adj, write w.
// PREV:  GEMM1 recomputes z_prev, apply bn_prev residual -> w_new (smem+global)
// STATS: GEMM2 computes z_cur, accumulate BN stats (atomics)
// POOLED:max sigmoid(w)*x2 -> g_pooled_u atomicMax
// LAST:  apply bn_prev + project to output row
// ---------------------------------------------------------------------------
template<bool INIT, bool PREV, bool STATS, bool POOLED, bool LAST>
__global__ void __launch_bounds__(256) k_edge(
    const float* __restrict__ adj, const float* __restrict__ ew0, const float* __restrict__ eb0,
    const float* __restrict__ EwP, const float* __restrict__ EbP, int bufP,
    const float* __restrict__ Ew,  const float* __restrict__ Eb,  int bufC,
    const float* __restrict__ e1w, const float* __restrict__ e1b,
    float* __restrict__ out)
{
    __shared__ float W_sh[64 * 68];
    __shared__ float e_sh[64 * 72];
    __shared__ float zcP_sh[64], zcC_sh[64], s_sh[64], sh_sh[64], e1w_sh[64];
    __shared__ float ssum[64], ssq[64];
    __shared__ unsigned pool_sh[64];
    __shared__ float sred[128];
    __shared__ float adj_sh[64];

    const int bid = blockIdx.x;
    const int bn = bid >> 2, tile = bid & 3;
    const int m0 = tile * 64;
    const int n = bn % N_, b = bn / N_;
    const int t = threadIdx.x;
    const int c = t & 15, r = t >> 4, c4 = c * 4;
    const int lane = t & 31, wp = t >> 5, grp = lane >> 2, tig = lane & 3;
    const int la = (wp & 3) * 16 + grp;        // local row
    const int lb = la + 8;
    const int ncol0 = (wp >> 2) * 32;
    const int m_a = m0 + la, m_b = m0 + lb;
    const bool va = m_a < M_, vb = m_b < M_;
    const int dst_a = m_a + (m_a >= n), dst_b = m_b + (m_b >= n);

    float* wbase = g_w + (size_t)bn * M_ * U_;

    // per-block constants into smem
    if (t < 64) {
        if (PREV || LAST) {
            zcP_sh[t] = __ldg(&EbP[t]) + g_xbuf[bufP][2][bn * U_ + t];
            s_sh[t] = g_ecoef[t];
            sh_sh[t] = g_ecoef[U_ + t];
        }
        if (STATS) {
            zcC_sh[t] = __ldg(&Eb[t]) + g_xbuf[bufC][2][bn * U_ + t];
            ssum[t] = 0.f; ssq[t] = 0.f;
        }
        if (POOLED) pool_sh[t] = 0u;
        if (LAST) e1w_sh[t] = __ldg(&e1w[t]);
        if (INIT) {
            int m = m0 + t;
            int dst = m + (m >= n);
            adj_sh[t] = (m < M_) ? __ldg(&adj[(size_t)bn * N_ + dst]) : 0.f;
        }
    }

    // W tile via cp.async (zero-fill invalid rows of tile 3 first: disjoint)
    if (!INIT) {
        if (tile == 3) {
            for (int idx = t; idx < 1024; idx += 256) {
                int rr = idx >> 4, q = (idx & 15) * 4;
                if (rr >= 7) *(float4*)&W_sh[rr * 68 + q] = make_float4(0.f, 0.f, 0.f, 0.f);
            }
        }
#pragma unroll
        for (int k = 0; k < 4; k++) {
            int idx = t + k * 256, rr = idx >> 4, q = (idx & 15) * 4;
            if (m0 + rr < M_)
                cp_async16((unsigned)__cvta_generic_to_shared(&W_sh[rr * 68 + q]),
                           &wbase[(size_t)(m0 + rr) * U_ + q]);
        }
        cp_commit();
    }

    // first E matrix (tf32) into e_sh
    {
        const float* E1 = (PREV || LAST) ? EwP : Ew;
        for (int idx = t; idx < 1024; idx += 256) {
            int k = idx >> 4, q = (idx & 15) * 4;
            float4 v = __ldg((const float4*)&E1[k * 64 + q]);
            v.x = __uint_as_float(to_tf32(v.x)); v.y = __uint_as_float(to_tf32(v.y));
            v.z = __uint_as_float(to_tf32(v.z)); v.w = __uint_as_float(to_tf32(v.w));
            *(float4*)&e_sh[k * 72 + q] = v;
        }
    }

    if (!INIT) cp_wait<0>();
    __syncthreads();

    if (INIT) {
        float4 ew04 = __ldg((const float4*)&ew0[c4]);
        float4 eb04 = __ldg((const float4*)&eb0[c4]);
#pragma unroll
        for (int j = 0; j < 4; j++) {
            int rr = 4 * r + j, m = m0 + rr;
            float a = adj_sh[rr];
            float4 w4;
            w4.x = lrelu(fmaf(a, ew04.x, eb04.x));
            w4.y = lrelu(fmaf(a, ew04.y, eb04.y));
            w4.z = lrelu(fmaf(a, ew04.z, eb04.z));
            w4.w = lrelu(fmaf(a, ew04.w, eb04.w));
            *(float4*)&W_sh[rr * 68 + c4] = w4;
            if (m < M_) *(float4*)&wbase[(size_t)m * U_ + c4] = w4;
        }
        __syncthreads();
    }

    // GEMM 1
    float cf[4][4];
    do_gemm(W_sh, e_sh, cf, la, ncol0, tig);

    const float* x4P = (PREV || LAST) ? &g_xbuf[bufP][3][(size_t)b * N_ * U_] : nullptr;
    const float* x2C = POOLED ? &g_xbuf[bufC][1][(size_t)b * N_ * U_] : nullptr;
    const float* x4C = STATS ? &g_xbuf[bufC][3][(size_t)b * N_ * U_] : nullptr;

    if (PREV || LAST) {
        __syncthreads();   // all GEMM1 reads of W_sh / e_sh complete
        if (PREV) {
            // swap in current-layer E while the apply phase runs
            for (int idx = t; idx < 1024; idx += 256) {
                int k = idx >> 4, q = (idx & 15) * 4;
                float4 v = __ldg((const float4*)&Ew[k * 64 + q]);
                v.x = __uint_as_float(to_tf32(v.x)); v.y = __uint_as_float(to_tf32(v.y));
                v.z = __uint_as_float(to_tf32(v.z)); v.w = __uint_as_float(to_tf32(v.w));
                *(float4*)&e_sh[k * 72 + q] = v;
            }
        }
        float pa = 0.f, pb = 0.f;
#pragma unroll
        for (int nt = 0; nt < 4; nt++) {
            int cc = ncol0 + nt * 8 + 2 * tig;
            float zc0 = zcP_sh[cc], zc1 = zcP_sh[cc + 1];
            float sc0 = s_sh[cc], sc1 = s_sh[cc + 1];
            float sf0 = sh_sh[cc], sf1 = sh_sh[cc + 1];
            if (va) {
                float2 x4v = *(const float2*)&x4P[dst_a * U_ + cc];
                float2 wv = *(const float2*)&W_sh[la * 68 + cc];
                float z0 = cf[nt][0] + (zc0 + x4v.x);
                float z1 = cf[nt][1] + (zc1 + x4v.y);
                float wn0 = wv.x + lrelu(fmaf(z0, sc0, sf0));
                float wn1 = wv.y + lrelu(fmaf(z1, sc1, sf1));
                if (LAST) {
                    pa += wn0 * e1w_sh[cc] + wn1 * e1w_sh[cc + 1];
                } else {
                    *(float2*)&W_sh[la * 68 + cc] = make_float2(wn0, wn1);
                    *(float2*)&wbase[(size_t)m_a * U_ + cc] = make_float2(wn0, wn1);
                }
            }
            if (vb) {
                float2 x4v = *(const float2*)&x4P[dst_b * U_ + cc];
                float2 wv = *(const float2*)&W_sh[lb * 68 + cc];
                float z0 = cf[nt][2] + (zc0 + x4v.x);
                float z1 = cf[nt][3] + (zc1 + x4v.y);
                float wn0 = wv.x + lrelu(fmaf(z0, sc0, sf0));
                float wn1 = wv.y + lrelu(fmaf(z1, sc1, sf1));
                if (LAST) {
                    pb += wn0 * e1w_sh[cc] + wn1 * e1w_sh[cc + 1];
                } else {
                    *(float2*)&W_sh[lb * 68 + cc] = make_float2(wn0, wn1);
                    *(float2*)&wbase[(size_t)m_b * U_ + cc] = make_float2(wn0, wn1);
                }
            }
        }
        if (LAST) {
            pa += __shfl_xor_sync(0xffffffffu, pa, 1);
            pa += __shfl_xor_sync(0xffffffffu, pa, 2);
            pb += __shfl_xor_sync(0xffffffffu, pb, 1);
            pb += __shfl_xor_sync(0xffffffffu, pb, 2);
            int nh = wp >> 2;
            if (tig == 0) { sred[la * 2 + nh] = pa; sred[lb * 2 + nh] = pb; }
            __syncthreads();
            if (t < 64) {
                int m = m0 + t;
                if (m < M_) {
                    int dst = m + (m >= n);
                    out[(size_t)bn * N_ + dst] = sred[t * 2] + sred[t * 2 + 1] + __ldg(&e1b[0]);
                }
            }
        }
        if (PREV) __syncthreads();   // W_sh updated + e_sh=Ew ready
    }

    if (STATS) {
        if (PREV) do_gemm(W_sh, e_sh, cf, la, ncol0, tig);   // GEMM 2 (else cf already stats)

        float es0[4], es1[4], eq0[4], eq1[4], pm0[4], pm1[4];
#pragma unroll
        for (int nt = 0; nt < 4; nt++) {
            int cc = ncol0 + nt * 8 + 2 * tig;
            float zc0 = zcC_sh[cc], zc1 = zcC_sh[cc + 1];
            float s0 = 0.f, s1 = 0.f, q0 = 0.f, q1 = 0.f;
            float p0 = -CUDART_INF_F, p1 = -CUDART_INF_F;
            if (va) {
                float2 x4v = *(const float2*)&x4C[dst_a * U_ + cc];
                float z0 = cf[nt][0] + (zc0 + x4v.x);
                float z1 = cf[nt][1] + (zc1 + x4v.y);
                s0 += z0; q0 = fmaf(z0, z0, q0);
                s1 += z1; q1 = fmaf(z1, z1, q1);
                if (POOLED) {
                    float2 wv = *(const float2*)&W_sh[la * 68 + cc];
                    float2 x2v = *(const float2*)&x2C[dst_a * U_ + cc];
                    p0 = x2v.x / (1.f + __expf(-wv.x));
                    p1 = x2v.y / (1.f + __expf(-wv.y));
                }
            }
            if (vb) {
                float2 x4v = *(const float2*)&x4C[dst_b * U_ + cc];
                float z0 = cf[nt][2] + (zc0 + x4v.x);
                float z1 = cf[nt][3] + (zc1 + x4v.y);
                s0 += z0; q0 = fmaf(z0, z0, q0);
                s1 += z1; q1 = fmaf(z1, z1, q1);
                if (POOLED) {
                    float2 wv = *(const float2*)&W_sh[lb * 68 + cc];
                    float2 x2v = *(const float2*)&x2C[dst_b * U_ + cc];
                    p0 = fmaxf(p0, x2v.x / (1.f + __expf(-wv.x)));
                    p1 = fmaxf(p1, x2v.y / (1.f + __expf(-wv.y)));
                }
            }
            es0[nt] = s0; es1[nt] = s1; eq0[nt] = q0; eq1[nt] = q1;
            pm0[nt] = p0; pm1[nt] = p1;
        }
        // reduce across grp (same columns, different rows)
#pragma unroll
        for (int off = 4; off <= 16; off <<= 1) {
#pragma unroll
            for (int nt = 0; nt < 4; nt++) {
                es0[nt] += __shfl_xor_sync(0xffffffffu, es0[nt], off);
                es1[nt] += __shfl_xor_sync(0xffffffffu, es1[nt], off);
                eq0[nt] += __shfl_xor_sync(0xffffffffu, eq0[nt], off);
                eq1[nt] += __shfl_xor_sync(0xffffffffu, eq1[nt], off);
                if (POOLED) {
                    pm0[nt] = fmaxf(pm0[nt], __shfl_xor_sync(0xffffffffu, pm0[nt], off));
                    pm1[nt] = fmaxf(pm1[nt], __shfl_xor_sync(0xffffffffu, pm1[nt], off));
                }
            }
        }
        if (grp == 0) {
#pragma unroll
            for (int nt = 0; nt < 4; nt++) {
                int cc = ncol0 + nt * 8 + 2 * tig;
                atomicAdd(&ssum[cc], es0[nt]);  atomicAdd(&ssum[cc + 1], es1[nt]);
                atomicAdd(&ssq[cc], eq0[nt]);   atomicAdd(&ssq[cc + 1], eq1[nt]);
                if (POOLED) {
                    atomicMax(&pool_sh[cc], enc_f(pm0[nt]));
                    atomicMax(&pool_sh[cc + 1], enc_f(pm1[nt]));
                }
            }
        }
        __syncthreads();
        if (t < 64) {
            atomicAdd(&g_estats[t], (double)ssum[t]);
            atomicAdd(&g_estats[U_ + t], (double)ssq[t]);
            if (POOLED) atomicMax(&g_pooled_u[bn * U_ + t], pool_sh[t]);
        }
    }
}

// ---------------------------------------------------------------------------
// Node kernel: 200 blocks x 16 bn each. h update + x1..x4 GEMVs.
// ---------------------------------------------------------------------------
__global__ void __launch_bounds__(256) k_node(
    const float* __restrict__ x, const float* __restrict__ l0w, const float* __restrict__ l0b,
    int first, int prevBuf, int outBuf, int initPool,
    const float* __restrict__ w1, const float* __restrict__ b1,
    const float* __restrict__ w2, const float* __restrict__ b2,
    const float* __restrict__ w3, const float* __restrict__ b3,
    const float* __restrict__ w4, const float* __restrict__ b4)
{
    __shared__ float hsh[U_];
    int t = threadIdx.x;
    int mat = t >> 6, col = t & 63;
    const float* W; const float* bb;
    switch (mat) {
        case 0:  W = w1; bb = b1; break;
        case 1:  W = w2; bb = b2; break;
        case 2:  W = w3; bb = b3; break;
        default: W = w4; bb = b4; break;
    }
    float bias = __ldg(&bb[col]);
    for (int i = 0; i < 16; i++) {
        int bn = blockIdx.x * 16 + i;
        if (t < U_) {
            float hv;
            if (first) {
                hv = lrelu(x[bn * 2] * __ldg(&l0w[t]) + x[bn * 2 + 1] * __ldg(&l0w[U_ + t]) + __ldg(&l0b[t]));
            } else {
                float zh = g_xbuf[prevBuf][0][bn * U_ + t] + dec_f(g_pooled_u[bn * U_ + t]);
                hv = g_h[bn * U_ + t] + lrelu(fmaf(zh, g_hcoef[t], g_hcoef[U_ + t]));
            }
            hsh[t] = hv;
            g_h[bn * U_ + t] = hv;
            if (initPool) g_pooled_u[bn * U_ + t] = 0u;
        }
        __syncthreads();
        float acc = bias;
#pragma unroll
        for (int k = 0; k < U_; k++) acc = fmaf(hsh[k], __ldg(&W[k * U_ + col]), acc);
        g_xbuf[outBuf][mat][bn * U_ + col] = acc;
        __syncthreads();
    }
}

// h BN stats: one block per u, reduce over all bn. Writes (not accumulates).
__global__ void __launch_bounds__(256) k_hstats(int bufC) {
    __shared__ float rs[256], rq[256];
    int u = blockIdx.x, t = threadIdx.x;
    float s = 0.f, q = 0.f;
    for (int i = t; i < BN_; i += 256) {
        float v = g_xbuf[bufC][0][i * U_ + u] + dec_f(g_pooled_u[i * U_ + u]);
        s += v; q = fmaf(v, v, q);
    }
    rs[t] = s; rq[t] = q;
    __syncthreads();
    for (int off = 128; off >= 1; off >>= 1) {
        if (t < off) { rs[t] += rs[t + off]; rq[t] += rq[t + off]; }
        __syncthreads();
    }
    if (t == 0) { g_hstats[u] = (double)rs[0]; g_hstats[U_ + u] = (double)rq[0]; }
}

__global__ void k_finalize(const float* __restrict__ hg, const float* __restrict__ hb,
                           const float* __restrict__ eg, const float* __restrict__ eb) {
    int u = threadIdx.x;  // 64
    double ecnt = (double)E_;
    float emean = (float)(g_estats[u] / ecnt);
    float evar  = (float)(g_estats[U_ + u] / ecnt) - emean * emean;
    float es = eg[u] * rsqrtf(evar + EPS_);
    g_ecoef[u] = es;
    g_ecoef[U_ + u] = eb[u] - emean * es;

    double hcnt = (double)BN_;
    float hmean = (float)(g_hstats[u] / hcnt);
    float hvar  = (float)(g_hstats[U_ + u] / hcnt) - hmean * hmean;
    float hs = hg[u] * rsqrtf(hvar + EPS_);
    g_hcoef[u] = hs;
    g_hcoef[U_ + u] = hb[u] - hmean * hs;

    g_estats[u] = 0.0; g_estats[U_ + u] = 0.0;
}

__global__ void k_zdiag(float* __restrict__ out) {
    int idx = blockIdx.x * 256 + threadIdx.x;
    if (idx >= BN_) return;
    out[(size_t)idx * N_ + (idx % N_)] = 0.f;
}

extern "C" void kernel_launch(void* const* d_in, const int* in_sizes, int n_in,
                              void* d_out, int out_size) {
    const float* x    = (const float*)d_in[0];
    const float* adj  = (const float*)d_in[1];
    const float* vl0w = (const float*)d_in[2];
    const float* vl0b = (const float*)d_in[3];
    const float* vw1  = (const float*)d_in[4];
    const float* vb1  = (const float*)d_in[5];
    const float* vw2  = (const float*)d_in[6];
    const float* vb2  = (const float*)d_in[7];
    const float* vw3  = (const float*)d_in[8];
    const float* vb3  = (const float*)d_in[9];
    const float* vw4  = (const float*)d_in[10];
    const float* vb4  = (const float*)d_in[11];
    const float* vbng = (const float*)d_in[12];
    const float* vbnb = (const float*)d_in[13];
    const float* el0w = (const float*)d_in[14];
    const float* el0b = (const float*)d_in[15];
    const float* ew   = (const float*)d_in[16];
    const float* eb   = (const float*)d_in[17];
    const float* ebng = (const float*)d_in[18];
    const float* ebnb = (const float*)d_in[19];
    const float* e1w  = (const float*)d_in[20];
    const float* e1b  = (const float*)d_in[21];
    float* out = (float*)d_out;

    auto S0 = k_edge<true,  false, true,  true,  false>;
    auto F1 = k_edge<false, true,  true,  true,  false>;
    auto F2 = k_edge<false, true,  true,  false, false>;
    auto AL = k_edge<false, false, false, false, true>;

    const float* W0 = ew,        *B0 = eb;
    const float* W1 = ew + 4096, *B1 = eb + 64;
    const float* W2 = ew + 8192, *B2 = eb + 128;
    const int G = BN_ * 4;

    // layer 0
    k_node<<<200, 256>>>(x, vl0w, vl0b, 1, 0, 0, 1,
                         vw1, vb1, vw2, vb2, vw3, vb3, vw4, vb4);
    S0<<<G, 256>>>(adj, el0w, el0b, nullptr, nullptr, 0, W0, B0, 0,
                   nullptr, nullptr, nullptr);
    k_hstats<<<64, 256>>>(0);
    k_finalize<<<1, 64>>>(vbng, vbnb, ebng, ebnb);

    // layer 1
    k_node<<<200, 256>>>(x, vl0w, vl0b, 0, 0, 1, 1,
                         vw1 + 4096, vb1 + 64, vw2 + 4096, vb2 + 64,
                         vw3 + 4096, vb3 + 64, vw4 + 4096, vb4 + 64);
    F1<<<G, 256>>>(nullptr, nullptr, nullptr, W0, B0, 0, W1, B1, 1,
                   nullptr, nullptr, nullptr);
    k_hstats<<<64, 256>>>(1);
    k_finalize<<<1, 64>>>(vbng + 64, vbnb + 64, ebng + 64, ebnb + 64);

    // layer 2
    k_node<<<200, 256>>>(x, vl0w, vl0b, 0, 1, 0, 0,
                         vw1 + 8192, vb1 + 128, vw2 + 8192, vb2 + 128,
                         vw3 + 8192, vb3 + 128, vw4 + 8192, vb4 + 128);
    F2<<<G, 256>>>(nullptr, nullptr, nullptr, W1, B1, 1, W2, B2, 0,
                   nullptr, nullptr, nullptr);
    k_finalize<<<1, 64>>>(vbng + 128, vbnb + 128, ebng + 128, ebnb + 128);

    // final apply + projection
    AL<<<G, 256>>>(nullptr, nullptr, nullptr, W2, B2, 0, nullptr, nullptr, 0,
                   e1w, e1b, out);
    k_zdiag<<<(BN_ + 255) / 256, 256>>>(out);
}